// round 1
// baseline (speedup 1.0000x reference)
#include <cuda_runtime.h>

#define DM 24
#define RD 10
#define NSEQ 512
#define NBATCH 8
#define ROWS (NBATCH * NSEQ)          // 4096
#define APAD 12                       // padded row stride for A/B tables

// Scratch (no runtime allocation allowed)
__device__ float g_A[ROWS * APAD];    // x_i @ W1[0:24] + b1, padded to 12
__device__ float g_Bv[ROWS * APAD];   // x_j @ W1[24:48],     padded to 12

// ---------------------------------------------------------------------------
// Kernel 1: per-row precompute of A_i and B_j (tiny: 4096 rows x 480 FMA)
// ---------------------------------------------------------------------------
__global__ void precompute_kernel(const float* __restrict__ x,
                                  const float* __restrict__ W1,
                                  const float* __restrict__ b1) {
    int row = blockIdx.x * blockDim.x + threadIdx.x;
    if (row >= ROWS) return;
    float xv[DM];
#pragma unroll
    for (int d = 0; d < DM; d++) xv[d] = x[(size_t)row * DM + d];
    float A[RD], Bv[RD];
#pragma unroll
    for (int r = 0; r < RD; r++) { A[r] = b1[r]; Bv[r] = 0.f; }
#pragma unroll
    for (int d = 0; d < DM; d++) {
        float xd = xv[d];
#pragma unroll
        for (int r = 0; r < RD; r++) {
            A[r]  = fmaf(xd, W1[d * RD + r], A[r]);
            Bv[r] = fmaf(xd, W1[(DM + d) * RD + r], Bv[r]);
        }
    }
#pragma unroll
    for (int r = 0; r < RD; r++) {
        g_A[row * APAD + r]  = A[r];
        g_Bv[row * APAD + r] = Bv[r];
    }
    g_A[row * APAD + 10] = 0.f;  g_A[row * APAD + 11] = 0.f;
    g_Bv[row * APAD + 10] = 0.f; g_Bv[row * APAD + 11] = 0.f;
}

// ---------------------------------------------------------------------------
// Kernel 2: main pairwise kernel. 1 warp per i, lanes stride j.
// ---------------------------------------------------------------------------
#define WARPS_PER_BLK 4

__global__ __launch_bounds__(WARPS_PER_BLK * 32, 1)
void pair_kernel(const float* __restrict__ q,
                 const float* __restrict__ coord,
                 const float* __restrict__ W1,
                 const float* __restrict__ W2,
                 const float* __restrict__ b2,
                 float* __restrict__ out) {
    // s_w1t[r][0..23] = W1c[d][r] (the |cdiff| block, rows 48..71 of W1)
    // s_w1t[r][24]    = W1[72][r] (q_overlap weight)
    // s_w1t[r][25]    = W1[73][r] (coord_dist weight)
    __shared__ float s_w1t[RD][28];
    // s_w2t[c][0..9] = W2[r][c], s_w2t[c][10] = b2[c]
    __shared__ float s_w2t[RD][12];

    int tid = threadIdx.x;
    for (int idx = tid; idx < RD * 28; idx += WARPS_PER_BLK * 32) {
        int r = idx / 28, k = idx % 28;
        float v = 0.f;
        if (k < 24)       v = W1[(48 + k) * RD + r];
        else if (k == 24) v = W1[72 * RD + r];
        else if (k == 25) v = W1[73 * RD + r];
        s_w1t[r][k] = v;
    }
    for (int idx = tid; idx < RD * 12; idx += WARPS_PER_BLK * 32) {
        int c = idx / 12, k = idx % 12;
        float v = 0.f;
        if (k < 10)       v = W2[k * RD + c];
        else if (k == 10) v = b2[c];
        s_w2t[c][k] = v;
    }
    __syncthreads();

    int warp = tid >> 5, lane = tid & 31;
    int i = blockIdx.x * WARPS_PER_BLK + warp;        // global row 0..4095
    int jbase = (i >> 9) << 9;                        // start of this batch

    // Row-i state (uniform across the warp; broadcast L1 hits)
    float ci[DM], qi[DM];
    const float4* ci4 = (const float4*)(coord + (size_t)i * DM);
    const float4* qi4 = (const float4*)(q + (size_t)i * DM);
#pragma unroll
    for (int k = 0; k < 6; k++) {
        float4 t = ci4[k];
        ci[4*k] = t.x; ci[4*k+1] = t.y; ci[4*k+2] = t.z; ci[4*k+3] = t.w;
        float4 u = qi4[k];
        qi[4*k] = u.x; qi[4*k+1] = u.y; qi[4*k+2] = u.z; qi[4*k+3] = u.w;
    }
    float Ai[RD];
    {
        const float4* a4 = (const float4*)(g_A + (size_t)i * APAD);
        float4 A0 = a4[0], A1 = a4[1], A2 = a4[2];
        Ai[0]=A0.x; Ai[1]=A0.y; Ai[2]=A0.z; Ai[3]=A0.w;
        Ai[4]=A1.x; Ai[5]=A1.y; Ai[6]=A1.z; Ai[7]=A1.w;
        Ai[8]=A2.x; Ai[9]=A2.y;
    }

    float sacc[RD], macc[RD];
#pragma unroll
    for (int c = 0; c < RD; c++) { sacc[c] = 0.f; macc[c] = 0.f; }

    for (int it = 0; it < NSEQ / 32; ++it) {
        int j = jbase + it * 32 + lane;

        const float4* cj4 = (const float4*)(coord + (size_t)j * DM);
        const float4* qj4 = (const float4*)(q + (size_t)j * DM);

        float a[DM];
        float d2 = 0.f, qd = 0.f;
#pragma unroll
        for (int k = 0; k < 6; k++) {
            float4 c4 = cj4[k];
            float4 q4 = qj4[k];
            float df;
            df = ci[4*k+0] - c4.x; a[4*k+0] = fabsf(df); d2 = fmaf(df, df, d2); qd = fmaf(qi[4*k+0], q4.x, qd);
            df = ci[4*k+1] - c4.y; a[4*k+1] = fabsf(df); d2 = fmaf(df, df, d2); qd = fmaf(qi[4*k+1], q4.y, qd);
            df = ci[4*k+2] - c4.z; a[4*k+2] = fabsf(df); d2 = fmaf(df, df, d2); qd = fmaf(qi[4*k+2], q4.z, qd);
            df = ci[4*k+3] - c4.w; a[4*k+3] = fabsf(df); d2 = fmaf(df, df, d2); qd = fmaf(qi[4*k+3], q4.w, qd);
        }
        float dist = sqrtf(d2);

        float Bj[RD];
        {
            const float4* b4 = (const float4*)(g_Bv + (size_t)j * APAD);
            float4 B0 = b4[0], B1 = b4[1], B2 = b4[2];
            Bj[0]=B0.x; Bj[1]=B0.y; Bj[2]=B0.z; Bj[3]=B0.w;
            Bj[4]=B1.x; Bj[5]=B1.y; Bj[6]=B1.z; Bj[7]=B1.w;
            Bj[8]=B2.x; Bj[9]=B2.y;
        }

        float h[RD];
#pragma unroll
        for (int r = 0; r < RD; r++) {
            const float4* wr = (const float4*)(&s_w1t[r][0]);
            float acc = Ai[r] + Bj[r];
            float4 w;
            w = wr[0];
            acc = fmaf(a[0],  w.x, acc); acc = fmaf(a[1],  w.y, acc);
            acc = fmaf(a[2],  w.z, acc); acc = fmaf(a[3],  w.w, acc);
            w = wr[1];
            acc = fmaf(a[4],  w.x, acc); acc = fmaf(a[5],  w.y, acc);
            acc = fmaf(a[6],  w.z, acc); acc = fmaf(a[7],  w.w, acc);
            w = wr[2];
            acc = fmaf(a[8],  w.x, acc); acc = fmaf(a[9],  w.y, acc);
            acc = fmaf(a[10], w.z, acc); acc = fmaf(a[11], w.w, acc);
            w = wr[3];
            acc = fmaf(a[12], w.x, acc); acc = fmaf(a[13], w.y, acc);
            acc = fmaf(a[14], w.z, acc); acc = fmaf(a[15], w.w, acc);
            w = wr[4];
            acc = fmaf(a[16], w.x, acc); acc = fmaf(a[17], w.y, acc);
            acc = fmaf(a[18], w.z, acc); acc = fmaf(a[19], w.w, acc);
            w = wr[5];
            acc = fmaf(a[20], w.x, acc); acc = fmaf(a[21], w.y, acc);
            acc = fmaf(a[22], w.z, acc); acc = fmaf(a[23], w.w, acc);
            w = wr[6];
            acc = fmaf(qd,   w.x, acc);
            acc = fmaf(dist, w.y, acc);
            h[r] = fmaxf(acc, 0.f);
        }

        bool off = (j != i);
#pragma unroll
        for (int c = 0; c < RD; c++) {
            const float4* wc = (const float4*)(&s_w2t[c][0]);
            float4 w0 = wc[0], w1v = wc[1], w2v = wc[2];
            float acc = w2v.z;  // b2[c]
            acc = fmaf(h[0], w0.x, acc);  acc = fmaf(h[1], w0.y, acc);
            acc = fmaf(h[2], w0.z, acc);  acc = fmaf(h[3], w0.w, acc);
            acc = fmaf(h[4], w1v.x, acc); acc = fmaf(h[5], w1v.y, acc);
            acc = fmaf(h[6], w1v.z, acc); acc = fmaf(h[7], w1v.w, acc);
            acc = fmaf(h[8], w2v.x, acc); acc = fmaf(h[9], w2v.y, acc);
            float rel = fmaxf(acc, 0.f);
            if (off) {
                sacc[c] += rel;
                macc[c] = fmaxf(macc[c], rel);
            }
        }
    }

    // Warp reduction across the 32 j-lanes (deterministic tree)
#pragma unroll
    for (int c = 0; c < RD; c++) {
#pragma unroll
        for (int o = 16; o > 0; o >>= 1) {
            sacc[c] += __shfl_xor_sync(0xffffffffu, sacc[c], o);
            macc[c] = fmaxf(macc[c], __shfl_xor_sync(0xffffffffu, macc[c], o));
        }
    }
    if (lane == 0) {
        const float inv = 1.0f / (float)(NSEQ - 1);
#pragma unroll
        for (int c = 0; c < RD; c++) {
            out[(size_t)i * RD + c] = sacc[c] * inv;
            out[(size_t)ROWS * RD + (size_t)i * RD + c] = macc[c];
        }
    }
}

// ---------------------------------------------------------------------------
extern "C" void kernel_launch(void* const* d_in, const int* in_sizes, int n_in,
                              void* d_out, int out_size) {
    const float* x     = (const float*)d_in[0];
    const float* q     = (const float*)d_in[1];
    const float* coord = (const float*)d_in[2];
    const float* W1    = (const float*)d_in[3];
    const float* b1    = (const float*)d_in[4];
    const float* W2    = (const float*)d_in[5];
    const float* b2    = (const float*)d_in[6];
    float* out = (float*)d_out;

    precompute_kernel<<<(ROWS + 127) / 128, 128>>>(x, W1, b1);
    pair_kernel<<<ROWS / WARPS_PER_BLK, WARPS_PER_BLK * 32>>>(q, coord, W1, W2, b2, out);
}

// round 4
// speedup vs baseline: 3.8286x; 3.8286x over previous
#include <cuda_runtime.h>

#define DM 24
#define RD 10
#define NSEQ 512
#define NBATCH 8
#define ROWS (NBATCH * NSEQ)          // 4096
#define APAD 12
#define CQS 52                        // padded row stride for staged cj/qj

typedef unsigned long long u64;

// Scratch (no runtime allocation allowed)
__device__ __align__(16) float g_A[ROWS * APAD];    // x_i @ W1[0:24] + b1
__device__ __align__(16) float g_Bv[ROWS * APAD];   // x_j @ W1[24:48]

// ---------------- f32x2 helpers (Blackwell packed math) ----------------
__device__ __forceinline__ u64 pk(float lo, float hi) {
    u64 r; asm("mov.b64 %0, {%1, %2};" : "=l"(r) : "f"(lo), "f"(hi)); return r;
}
__device__ __forceinline__ void upk(float& lo, float& hi, u64 v) {
    asm("mov.b64 {%0, %1}, %2;" : "=f"(lo), "=f"(hi) : "l"(v));
}
__device__ __forceinline__ u64 f2fma(u64 a, u64 b, u64 c) {
    u64 d; asm("fma.rn.f32x2 %0, %1, %2, %3;" : "=l"(d) : "l"(a), "l"(b), "l"(c)); return d;
}
__device__ __forceinline__ u64 f2add(u64 a, u64 b) {
    u64 d; asm("add.rn.f32x2 %0, %1, %2;" : "=l"(d) : "l"(a), "l"(b)); return d;
}

// ---------------------------------------------------------------------------
// Kernel 1: per-row precompute of A_i = x_i@W1[0:24]+b1 and B_j = x_j@W1[24:48]
// ---------------------------------------------------------------------------
__global__ void precompute_kernel(const float* __restrict__ x,
                                  const float* __restrict__ W1,
                                  const float* __restrict__ b1) {
    int row = blockIdx.x * blockDim.x + threadIdx.x;
    if (row >= ROWS) return;
    float xv[DM];
#pragma unroll
    for (int d = 0; d < DM; d++) xv[d] = x[(size_t)row * DM + d];
    float A[RD], Bv[RD];
#pragma unroll
    for (int r = 0; r < RD; r++) { A[r] = b1[r]; Bv[r] = 0.f; }
#pragma unroll
    for (int d = 0; d < DM; d++) {
        float xd = xv[d];
#pragma unroll
        for (int r = 0; r < RD; r++) {
            A[r]  = fmaf(xd, W1[d * RD + r], A[r]);
            Bv[r] = fmaf(xd, W1[(DM + d) * RD + r], Bv[r]);
        }
    }
#pragma unroll
    for (int r = 0; r < RD; r++) {
        g_A[row * APAD + r]  = A[r];
        g_Bv[row * APAD + r] = Bv[r];
    }
    g_A[row * APAD + 10] = 0.f;  g_A[row * APAD + 11] = 0.f;
    g_Bv[row * APAD + 10] = 0.f; g_Bv[row * APAD + 11] = 0.f;
}

// ---------------------------------------------------------------------------
// Kernel 2: pairwise. 1 warp per i; per superiter the BLOCK stages a 64-row
// j-chunk (coord/q/B) into shared; each lane handles j = jb+lane and jb+32+lane.
// ---------------------------------------------------------------------------
__global__ __launch_bounds__(128, 4)
void pair_kernel(const float* __restrict__ q,
                 const float* __restrict__ coord,
                 const float* __restrict__ W1,
                 const float* __restrict__ W2,
                 const float* __restrict__ b2,
                 float* __restrict__ out) {
    __shared__ __align__(16) float s_cq[64][CQS];  // [r][0:24)=coord_j, [24:48)=q_j (208B stride)
    __shared__ __align__(16) float s_bj[64][14];   // B_j rows (56B stride; float2 access only)
    __shared__ __align__(16) float s_w1[26][12];   // s_w1[k][r]: k<24 |cdiff| rows, 24=qov, 25=dist
    __shared__ __align__(16) float s_w2[10][12];   // s_w2[rh][c] = W2[rh][c]
    __shared__ __align__(16) float s_ciq[4][CQS];  // per-warp: ci (0..23), qi (24..47)
    __shared__ __align__(16) float s_ai[4][12];    // per-warp: A_i

    const int tid = threadIdx.x;
    const int w = tid >> 5, lane = tid & 31;
    const int i = blockIdx.x * 4 + w;
    const int jbase = i & ~(NSEQ - 1);

    // --- one-time fills ---
    for (int idx = tid; idx < 26 * 12; idx += 128) {
        int d = idx / 12, r = idx % 12;
        float v = 0.f;
        if (r < RD) {
            int row = (d < 24) ? (48 + d) : (d == 24 ? 72 : 73);
            v = W1[row * RD + r];
        }
        s_w1[d][r] = v;
    }
    for (int idx = tid; idx < 10 * 12; idx += 128) {
        int rh = idx / 12, c = idx % 12;
        s_w2[rh][c] = (c < RD) ? W2[rh * RD + c] : 0.f;
    }
    if (lane < DM) {
        s_ciq[w][lane]      = coord[(size_t)i * DM + lane];
        s_ciq[w][24 + lane] = q[(size_t)i * DM + lane];
    }
    if (lane < 12) s_ai[w][lane] = g_A[i * APAD + lane];

    u64 b2p[5];
#pragma unroll
    for (int t = 0; t < 5; t++) b2p[t] = pk(b2[2 * t], b2[2 * t + 1]);

    float sacc[RD], macc[RD];
#pragma unroll
    for (int c = 0; c < RD; c++) { sacc[c] = 0.f; macc[c] = 0.f; }

    for (int it = 0; it < NSEQ / 64; ++it) {
        const int jb = jbase + it * 64;
        __syncthreads();
        // --- stage 64 j-rows: coord+q (float4, 208B stride OK) and B (float2, 56B stride) ---
        {
            const float4* gc = (const float4*)(coord + (size_t)jb * DM);
            const float4* gq = (const float4*)(q + (size_t)jb * DM);
#pragma unroll
            for (int k = tid; k < 384; k += 128) {          // 64*24/4
                int r = k / 6, c = (k % 6) * 4;
                *(float4*)&s_cq[r][c]      = gc[k];
                *(float4*)&s_cq[r][24 + c] = gq[k];
            }
            const float2* gb = (const float2*)(g_Bv + (size_t)jb * APAD);
#pragma unroll
            for (int k = tid; k < 384; k += 128) {          // 64*12/2
                int r = k / 6, c = (k % 6) * 2;
                *(float2*)&s_bj[r][c] = gb[k];
            }
        }
        __syncthreads();

        // --- per-lane: two pairs (i, jb+lane) and (i, jb+32+lane) ---
        u64 h2a[5], h2b[5];
#pragma unroll
        for (int t = 0; t < 5; t++) {
            u64 ai = *(const u64*)&s_ai[w][2 * t];
            h2a[t] = f2add(ai, *(const u64*)&s_bj[lane][2 * t]);
            h2b[t] = f2add(ai, *(const u64*)&s_bj[32 + lane][2 * t]);
        }
        u64 dqa = 0ull, dqb = 0ull;   // {d2, qdot}

#pragma unroll
        for (int kk = 0; kk < 6; ++kk) {
            float4 ci4 = *(const float4*)&s_ciq[w][4 * kk];
            float4 qi4 = *(const float4*)&s_ciq[w][24 + 4 * kk];
            float4 cj0 = *(const float4*)&s_cq[lane][4 * kk];
            float4 qj0 = *(const float4*)&s_cq[lane][24 + 4 * kk];
            float4 cj1 = *(const float4*)&s_cq[32 + lane][4 * kk];
            float4 qj1 = *(const float4*)&s_cq[32 + lane][24 + 4 * kk];
            const float* cip = &ci4.x; const float* qip = &qi4.x;
            const float* c0 = &cj0.x;  const float* q0 = &qj0.x;
            const float* c1 = &cj1.x;  const float* q1 = &qj1.x;
#pragma unroll
            for (int e = 0; e < 4; e++) {
                const int d = 4 * kk + e;
                float df0 = cip[e] - c0[e];
                float df1 = cip[e] - c1[e];
                dqa = f2fma(pk(df0, qip[e]), pk(df0, q0[e]), dqa);
                dqb = f2fma(pk(df1, qip[e]), pk(df1, q1[e]), dqb);
                float ad0 = fabsf(df0), ad1 = fabsf(df1);
                u64 a0 = pk(ad0, ad0), a1 = pk(ad1, ad1);
#pragma unroll
                for (int t = 0; t < 5; t++) {
                    u64 wv = *(const u64*)&s_w1[d][2 * t];
                    h2a[t] = f2fma(a0, wv, h2a[t]);
                    h2b[t] = f2fma(a1, wv, h2b[t]);
                }
            }
        }
        // tail features: q_overlap, coord_dist
        float d2a, qda, d2b, qdb;
        upk(d2a, qda, dqa); upk(d2b, qdb, dqb);
        float dsa = sqrtf(d2a), dsb = sqrtf(d2b);
        u64 qpa = pk(qda, qda), qpb = pk(qdb, qdb);
        u64 dpa = pk(dsa, dsa), dpb = pk(dsb, dsb);
#pragma unroll
        for (int t = 0; t < 5; t++) {
            u64 wq = *(const u64*)&s_w1[24][2 * t];
            u64 wd = *(const u64*)&s_w1[25][2 * t];
            h2a[t] = f2fma(qpa, wq, h2a[t]);
            h2b[t] = f2fma(qpb, wq, h2b[t]);
            h2a[t] = f2fma(dpa, wd, h2a[t]);
            h2b[t] = f2fma(dpb, wd, h2b[t]);
        }
        // relu -> scalars
        float ha[RD], hb[RD];
#pragma unroll
        for (int t = 0; t < 5; t++) {
            upk(ha[2 * t], ha[2 * t + 1], h2a[t]);
            upk(hb[2 * t], hb[2 * t + 1], h2b[t]);
        }
#pragma unroll
        for (int r = 0; r < RD; r++) { ha[r] = fmaxf(ha[r], 0.f); hb[r] = fmaxf(hb[r], 0.f); }

        // layer 2 (packed over output-channel pairs)
        u64 r2a[5], r2b[5];
#pragma unroll
        for (int t = 0; t < 5; t++) { r2a[t] = b2p[t]; r2b[t] = b2p[t]; }
#pragma unroll
        for (int rh = 0; rh < RD; rh++) {
            u64 hha = pk(ha[rh], ha[rh]);
            u64 hhb = pk(hb[rh], hb[rh]);
#pragma unroll
            for (int t = 0; t < 5; t++) {
                u64 wv = *(const u64*)&s_w2[rh][2 * t];
                r2a[t] = f2fma(hha, wv, r2a[t]);
                r2b[t] = f2fma(hhb, wv, r2b[t]);
            }
        }
        // relu + masked accumulate
        const bool oa = (jb + lane) != i;
        const bool ob = (jb + 32 + lane) != i;
#pragma unroll
        for (int t = 0; t < 5; t++) {
            float r0, r1;
            upk(r0, r1, r2a[t]);
            r0 = fmaxf(r0, 0.f); r1 = fmaxf(r1, 0.f);
            if (oa) {
                sacc[2 * t]     += r0;  macc[2 * t]     = fmaxf(macc[2 * t], r0);
                sacc[2 * t + 1] += r1;  macc[2 * t + 1] = fmaxf(macc[2 * t + 1], r1);
            }
            upk(r0, r1, r2b[t]);
            r0 = fmaxf(r0, 0.f); r1 = fmaxf(r1, 0.f);
            if (ob) {
                sacc[2 * t]     += r0;  macc[2 * t]     = fmaxf(macc[2 * t], r0);
                sacc[2 * t + 1] += r1;  macc[2 * t + 1] = fmaxf(macc[2 * t + 1], r1);
            }
        }
    }

    // warp reduction across j-lanes (deterministic tree)
#pragma unroll
    for (int c = 0; c < RD; c++) {
#pragma unroll
        for (int o = 16; o > 0; o >>= 1) {
            sacc[c] += __shfl_xor_sync(0xffffffffu, sacc[c], o);
            macc[c] = fmaxf(macc[c], __shfl_xor_sync(0xffffffffu, macc[c], o));
        }
    }
    if (lane == 0) {
        const float inv = 1.0f / (float)(NSEQ - 1);
#pragma unroll
        for (int c = 0; c < RD; c++) {
            out[(size_t)i * RD + c] = sacc[c] * inv;
            out[(size_t)ROWS * RD + (size_t)i * RD + c] = macc[c];
        }
    }
}

// ---------------------------------------------------------------------------
extern "C" void kernel_launch(void* const* d_in, const int* in_sizes, int n_in,
                              void* d_out, int out_size) {
    const float* x     = (const float*)d_in[0];
    const float* q     = (const float*)d_in[1];
    const float* coord = (const float*)d_in[2];
    const float* W1    = (const float*)d_in[3];
    const float* b1    = (const float*)d_in[4];
    const float* W2    = (const float*)d_in[5];
    const float* b2    = (const float*)d_in[6];
    float* out = (float*)d_out;

    precompute_kernel<<<(ROWS + 127) / 128, 128>>>(x, W1, b1);
    pair_kernel<<<ROWS / 4, 128>>>(q, coord, W1, W2, b2, out);
}

// round 6
// speedup vs baseline: 4.0510x; 1.0581x over previous
#include <cuda_runtime.h>

#define DM 24
#define RD 10
#define NSEQ 512
#define NBATCH 8
#define ROWS (NBATCH * NSEQ)          // 4096
#define APAD 12
#define CQS 52                        // padded row stride for staged cj/qj
#define JCH 128                       // j-chunk rows per superiter

typedef unsigned long long u64;

// Scratch (no runtime allocation allowed)
__device__ __align__(16) float g_A[ROWS * APAD];    // x_i @ W1[0:24] + b1
__device__ __align__(16) float g_Bv[ROWS * APAD];   // x_j @ W1[24:48]

// ---------------- f32x2 helpers (Blackwell packed math) ----------------
__device__ __forceinline__ u64 pk(float lo, float hi) {
    u64 r; asm("mov.b64 %0, {%1, %2};" : "=l"(r) : "f"(lo), "f"(hi)); return r;
}
__device__ __forceinline__ void upk(float& lo, float& hi, u64 v) {
    asm("mov.b64 {%0, %1}, %2;" : "=f"(lo), "=f"(hi) : "l"(v));
}
__device__ __forceinline__ u64 f2fma(u64 a, u64 b, u64 c) {
    u64 d; asm("fma.rn.f32x2 %0, %1, %2, %3;" : "=l"(d) : "l"(a), "l"(b), "l"(c)); return d;
}
__device__ __forceinline__ u64 f2add(u64 a, u64 b) {
    u64 d; asm("add.rn.f32x2 %0, %1, %2;" : "=l"(d) : "l"(a), "l"(b)); return d;
}

// ---------------------------------------------------------------------------
// Kernel 1: per-row precompute of A_i = x_i@W1[0:24]+b1 and B_j = x_j@W1[24:48]
// ---------------------------------------------------------------------------
__global__ void precompute_kernel(const float* __restrict__ x,
                                  const float* __restrict__ W1,
                                  const float* __restrict__ b1) {
    int row = blockIdx.x * blockDim.x + threadIdx.x;
    if (row >= ROWS) return;
    float xv[DM];
#pragma unroll
    for (int d = 0; d < DM; d++) xv[d] = x[(size_t)row * DM + d];
    float A[RD], Bv[RD];
#pragma unroll
    for (int r = 0; r < RD; r++) { A[r] = b1[r]; Bv[r] = 0.f; }
#pragma unroll
    for (int d = 0; d < DM; d++) {
        float xd = xv[d];
#pragma unroll
        for (int r = 0; r < RD; r++) {
            A[r]  = fmaf(xd, W1[d * RD + r], A[r]);
            Bv[r] = fmaf(xd, W1[(DM + d) * RD + r], Bv[r]);
        }
    }
#pragma unroll
    for (int r = 0; r < RD; r++) {
        g_A[row * APAD + r]  = A[r];
        g_Bv[row * APAD + r] = Bv[r];
    }
    g_A[row * APAD + 10] = 0.f;  g_A[row * APAD + 11] = 0.f;
    g_Bv[row * APAD + 10] = 0.f; g_Bv[row * APAD + 11] = 0.f;
}

// ---------------------------------------------------------------------------
// Kernel 2: pairwise. 1 warp per i; per superiter the BLOCK stages a 128-row
// j-chunk; each lane handles 4 j's (jb+lane, +32, +64, +96) so every
// warp-uniform weight LDS is amortized over 4 pairs.
// ---------------------------------------------------------------------------
__global__ __launch_bounds__(128, 3)
void pair_kernel(const float* __restrict__ q,
                 const float* __restrict__ coord,
                 const float* __restrict__ W1,
                 const float* __restrict__ W2,
                 const float* __restrict__ b2,
                 float* __restrict__ out) {
    __shared__ __align__(16) float s_cq[JCH][CQS];  // [r][0:24)=coord_j, [24:48)=q_j (208B stride)
    __shared__ __align__(16) float s_bj[JCH][14];   // B_j rows (56B stride; float2/u64 access only)
    __shared__ __align__(16) float s_w1[26][12];    // [k][r]: k<24 |cdiff| rows, 24=qov, 25=dist
    __shared__ __align__(16) float s_w2[10][12];    // [rh][c] = W2[rh][c]
    __shared__ __align__(16) float s_ciq[4][CQS];   // per-warp: ci (0..23), qi (24..47)
    __shared__ __align__(16) float s_ai[4][12];     // per-warp: A_i

    const int tid = threadIdx.x;
    const int w = tid >> 5, lane = tid & 31;
    const int i = blockIdx.x * 4 + w;
    const int jbase = i & ~(NSEQ - 1);

    // --- one-time fills ---
    for (int idx = tid; idx < 26 * 12; idx += 128) {
        int d = idx / 12, r = idx % 12;
        float v = 0.f;
        if (r < RD) {
            int row = (d < 24) ? (48 + d) : (d == 24 ? 72 : 73);
            v = W1[row * RD + r];
        }
        s_w1[d][r] = v;
    }
    for (int idx = tid; idx < 10 * 12; idx += 128) {
        int rh = idx / 12, c = idx % 12;
        s_w2[rh][c] = (c < RD) ? W2[rh * RD + c] : 0.f;
    }
    if (lane < DM) {
        s_ciq[w][lane]      = coord[(size_t)i * DM + lane];
        s_ciq[w][24 + lane] = q[(size_t)i * DM + lane];
    }
    if (lane < 12) s_ai[w][lane] = g_A[i * APAD + lane];

    u64 b2p[5];
#pragma unroll
    for (int t = 0; t < 5; t++) b2p[t] = pk(b2[2 * t], b2[2 * t + 1]);

    float sacc[RD], macc[RD];
#pragma unroll
    for (int c = 0; c < RD; c++) { sacc[c] = 0.f; macc[c] = 0.f; }

    for (int it = 0; it < NSEQ / JCH; ++it) {
        const int jb = jbase + it * JCH;
        __syncthreads();
        // --- stage 128 j-rows (coalesced) ---
        {
            const float4* gc = (const float4*)(coord + (size_t)jb * DM);
            const float4* gq = (const float4*)(q + (size_t)jb * DM);
#pragma unroll
            for (int k = tid; k < JCH * 6; k += 128) {       // 128*24/4
                int r = k / 6, c = (k % 6) * 4;
                *(float4*)&s_cq[r][c]      = gc[k];
                *(float4*)&s_cq[r][24 + c] = gq[k];
            }
            const float2* gb = (const float2*)(g_Bv + (size_t)jb * APAD);
#pragma unroll
            for (int k = tid; k < JCH * 6; k += 128) {       // 128*12/2
                int r = k / 6, c = (k % 6) * 2;
                *(float2*)&s_bj[r][c] = gb[k];
            }
        }
        __syncthreads();

        // --- per-lane: 4 pairs (i, jb + lane + 32x) ---
        u64 h2[4][5];
        u64 dq[4];
#pragma unroll
        for (int x = 0; x < 4; x++) {
            dq[x] = 0ull;
#pragma unroll
            for (int t = 0; t < 5; t++) {
                u64 ai = *(const u64*)&s_ai[w][2 * t];
                h2[x][t] = f2add(ai, *(const u64*)&s_bj[32 * x + lane][2 * t]);
            }
        }

#pragma unroll
        for (int kk = 0; kk < 6; ++kk) {
            float4 ci4 = *(const float4*)&s_ciq[w][4 * kk];
            float4 qi4 = *(const float4*)&s_ciq[w][24 + 4 * kk];
            float4 cj[4], qj[4];
#pragma unroll
            for (int x = 0; x < 4; x++) {
                cj[x] = *(const float4*)&s_cq[32 * x + lane][4 * kk];
                qj[x] = *(const float4*)&s_cq[32 * x + lane][24 + 4 * kk];
            }
            const float* cip = &ci4.x; const float* qip = &qi4.x;
#pragma unroll
            for (int e = 0; e < 4; e++) {
                const int d = 4 * kk + e;
                u64 av[4];
#pragma unroll
                for (int x = 0; x < 4; x++) {
                    const float* cjp = &cj[x].x;
                    const float* qjp = &qj[x].x;
                    float df = cip[e] - cjp[e];
                    dq[x] = f2fma(pk(df, qip[e]), pk(df, qjp[e]), dq[x]);
                    float ad = fabsf(df);
                    av[x] = pk(ad, ad);
                }
#pragma unroll
                for (int t = 0; t < 5; t++) {
                    u64 wv = *(const u64*)&s_w1[d][2 * t];
                    h2[0][t] = f2fma(av[0], wv, h2[0][t]);
                    h2[1][t] = f2fma(av[1], wv, h2[1][t]);
                    h2[2][t] = f2fma(av[2], wv, h2[2][t]);
                    h2[3][t] = f2fma(av[3], wv, h2[3][t]);
                }
            }
        }
        // tail features: q_overlap, coord_dist
        u64 qp[4], dp[4];
#pragma unroll
        for (int x = 0; x < 4; x++) {
            float d2, qd;
            upk(d2, qd, dq[x]);
            float ds = sqrtf(d2);
            qp[x] = pk(qd, qd);
            dp[x] = pk(ds, ds);
        }
#pragma unroll
        for (int t = 0; t < 5; t++) {
            u64 wq = *(const u64*)&s_w1[24][2 * t];
            u64 wd = *(const u64*)&s_w1[25][2 * t];
#pragma unroll
            for (int x = 0; x < 4; x++) {
                h2[x][t] = f2fma(qp[x], wq, h2[x][t]);
                h2[x][t] = f2fma(dp[x], wd, h2[x][t]);
            }
        }
        // relu -> packed duplicated hidden values
        float ha[4][RD];
#pragma unroll
        for (int x = 0; x < 4; x++) {
#pragma unroll
            for (int t = 0; t < 5; t++) {
                float lo, hi;
                upk(lo, hi, h2[x][t]);
                ha[x][2 * t]     = fmaxf(lo, 0.f);
                ha[x][2 * t + 1] = fmaxf(hi, 0.f);
            }
        }

        // layer 2: each weight LDS feeds 4 pairs
        u64 r2[4][5];
#pragma unroll
        for (int x = 0; x < 4; x++)
#pragma unroll
            for (int t = 0; t < 5; t++) r2[x][t] = b2p[t];
#pragma unroll
        for (int rh = 0; rh < RD; rh++) {
            u64 hh[4];
#pragma unroll
            for (int x = 0; x < 4; x++) hh[x] = pk(ha[x][rh], ha[x][rh]);
#pragma unroll
            for (int t = 0; t < 5; t++) {
                u64 wv = *(const u64*)&s_w2[rh][2 * t];
                r2[0][t] = f2fma(hh[0], wv, r2[0][t]);
                r2[1][t] = f2fma(hh[1], wv, r2[1][t]);
                r2[2][t] = f2fma(hh[2], wv, r2[2][t]);
                r2[3][t] = f2fma(hh[3], wv, r2[3][t]);
            }
        }
        // relu + masked accumulate
#pragma unroll
        for (int x = 0; x < 4; x++) {
            const bool off = (jb + 32 * x + lane) != i;
            if (off) {
#pragma unroll
                for (int t = 0; t < 5; t++) {
                    float r0, r1;
                    upk(r0, r1, r2[x][t]);
                    r0 = fmaxf(r0, 0.f); r1 = fmaxf(r1, 0.f);
                    sacc[2 * t]     += r0;  macc[2 * t]     = fmaxf(macc[2 * t], r0);
                    sacc[2 * t + 1] += r1;  macc[2 * t + 1] = fmaxf(macc[2 * t + 1], r1);
                }
            }
        }
    }

    // warp reduction across j-lanes (deterministic tree)
#pragma unroll
    for (int c = 0; c < RD; c++) {
#pragma unroll
        for (int o = 16; o > 0; o >>= 1) {
            sacc[c] += __shfl_xor_sync(0xffffffffu, sacc[c], o);
            macc[c] = fmaxf(macc[c], __shfl_xor_sync(0xffffffffu, macc[c], o));
        }
    }
    if (lane == 0) {
        const float inv = 1.0f / (float)(NSEQ - 1);
#pragma unroll
        for (int c = 0; c < RD; c++) {
            out[(size_t)i * RD + c] = sacc[c] * inv;
            out[(size_t)ROWS * RD + (size_t)i * RD + c] = macc[c];
        }
    }
}

// ---------------------------------------------------------------------------
extern "C" void kernel_launch(void* const* d_in, const int* in_sizes, int n_in,
                              void* d_out, int out_size) {
    const float* x     = (const float*)d_in[0];
    const float* q     = (const float*)d_in[1];
    const float* coord = (const float*)d_in[2];
    const float* W1    = (const float*)d_in[3];
    const float* b1    = (const float*)d_in[4];
    const float* W2    = (const float*)d_in[5];
    const float* b2    = (const float*)d_in[6];
    float* out = (float*)d_out;

    precompute_kernel<<<(ROWS + 127) / 128, 128>>>(x, W1, b1);
    pair_kernel<<<ROWS / 4, 128>>>(q, coord, W1, W2, b2, out);
}

// round 9
// speedup vs baseline: 4.0625x; 1.0028x over previous
#include <cuda_runtime.h>

#define DM 24
#define RD 10
#define NSEQ 512
#define NBATCH 8
#define ROWS (NBATCH * NSEQ)          // 4096
#define APAD 12
#define CQS 52                        // padded row stride for staged cj/qj
#define JCH 128                       // j-chunk rows per superiter

typedef unsigned long long u64;

// Scratch (no runtime allocation allowed)
__device__ __align__(16) float g_A[ROWS * APAD];    // x_i @ W1[0:24] + b1
__device__ __align__(16) float g_Bv[ROWS * APAD];   // x_j @ W1[24:48]

// ---------------- f32x2 helpers (Blackwell packed math) ----------------
__device__ __forceinline__ u64 pk(float lo, float hi) {
    u64 r; asm("mov.b64 %0, {%1, %2};" : "=l"(r) : "f"(lo), "f"(hi)); return r;
}
__device__ __forceinline__ void upk(float& lo, float& hi, u64 v) {
    asm("mov.b64 {%0, %1}, %2;" : "=f"(lo), "=f"(hi) : "l"(v));
}
__device__ __forceinline__ u64 f2fma(u64 a, u64 b, u64 c) {
    u64 d; asm("fma.rn.f32x2 %0, %1, %2, %3;" : "=l"(d) : "l"(a), "l"(b), "l"(c)); return d;
}
__device__ __forceinline__ u64 f2add(u64 a, u64 b) {
    u64 d; asm("add.rn.f32x2 %0, %1, %2;" : "=l"(d) : "l"(a), "l"(b)); return d;
}

// ---------------------------------------------------------------------------
// Kernel 1: per-row precompute of A_i = x_i@W1[0:24]+b1 and B_j = x_j@W1[24:48]
// ---------------------------------------------------------------------------
__global__ void precompute_kernel(const float* __restrict__ x,
                                  const float* __restrict__ W1,
                                  const float* __restrict__ b1) {
    int row = blockIdx.x * blockDim.x + threadIdx.x;
    if (row >= ROWS) return;
    float xv[DM];
#pragma unroll
    for (int d = 0; d < DM; d++) xv[d] = x[(size_t)row * DM + d];
    float A[RD], Bv[RD];
#pragma unroll
    for (int r = 0; r < RD; r++) { A[r] = b1[r]; Bv[r] = 0.f; }
#pragma unroll
    for (int d = 0; d < DM; d++) {
        float xd = xv[d];
#pragma unroll
        for (int r = 0; r < RD; r++) {
            A[r]  = fmaf(xd, W1[d * RD + r], A[r]);
            Bv[r] = fmaf(xd, W1[(DM + d) * RD + r], Bv[r]);
        }
    }
#pragma unroll
    for (int r = 0; r < RD; r++) {
        g_A[row * APAD + r]  = A[r];
        g_Bv[row * APAD + r] = Bv[r];
    }
    g_A[row * APAD + 10] = 0.f;  g_A[row * APAD + 11] = 0.f;
    g_Bv[row * APAD + 10] = 0.f; g_Bv[row * APAD + 11] = 0.f;
}

// ---------------------------------------------------------------------------
// Kernel 2: pairwise. 1 warp per i; per superiter the BLOCK stages a 128-row
// j-chunk; each lane handles 4 j's (jb+lane, +32, +64, +96).
// d2/qdot kept as SCALAR fma chains (no pk movs); only the weight matmuls
// use packed f32x2.
// ---------------------------------------------------------------------------
__global__ __launch_bounds__(128, 4)
void pair_kernel(const float* __restrict__ q,
                 const float* __restrict__ coord,
                 const float* __restrict__ W1,
                 const float* __restrict__ W2,
                 const float* __restrict__ b2,
                 float* __restrict__ out) {
    __shared__ __align__(16) float s_cq[JCH][CQS];  // [r][0:24)=coord_j, [24:48)=q_j (208B stride)
    __shared__ __align__(16) float s_bj[JCH][14];   // B_j rows (56B stride; float2/u64 access only)
    __shared__ __align__(16) float s_w1[26][12];    // [k][r]: k<24 |cdiff| rows, 24=qov, 25=dist
    __shared__ __align__(16) float s_w2[10][12];    // [rh][c] = W2[rh][c]
    __shared__ __align__(16) float s_ciq[4][CQS];   // per-warp: ci (0..23), qi (24..47)
    __shared__ __align__(16) float s_ai[4][12];     // per-warp: A_i

    const int tid = threadIdx.x;
    const int w = tid >> 5, lane = tid & 31;
    const int i = blockIdx.x * 4 + w;
    const int jbase = i & ~(NSEQ - 1);

    // --- one-time fills ---
    for (int idx = tid; idx < 26 * 12; idx += 128) {
        int d = idx / 12, r = idx % 12;
        float v = 0.f;
        if (r < RD) {
            int row = (d < 24) ? (48 + d) : (d == 24 ? 72 : 73);
            v = W1[row * RD + r];
        }
        s_w1[d][r] = v;
    }
    for (int idx = tid; idx < 10 * 12; idx += 128) {
        int rh = idx / 12, c = idx % 12;
        s_w2[rh][c] = (c < RD) ? W2[rh * RD + c] : 0.f;
    }
    if (lane < DM) {
        s_ciq[w][lane]      = coord[(size_t)i * DM + lane];
        s_ciq[w][24 + lane] = q[(size_t)i * DM + lane];
    }
    if (lane < 12) s_ai[w][lane] = g_A[i * APAD + lane];

    u64 b2p[5];
#pragma unroll
    for (int t = 0; t < 5; t++) b2p[t] = pk(b2[2 * t], b2[2 * t + 1]);

    float sacc[RD], macc[RD];
#pragma unroll
    for (int c = 0; c < RD; c++) { sacc[c] = 0.f; macc[c] = 0.f; }

    for (int it = 0; it < NSEQ / JCH; ++it) {
        const int jb = jbase + it * JCH;
        __syncthreads();
        // --- stage 128 j-rows (coalesced) ---
        {
            const float4* gc = (const float4*)(coord + (size_t)jb * DM);
            const float4* gq = (const float4*)(q + (size_t)jb * DM);
#pragma unroll
            for (int k = tid; k < JCH * 6; k += 128) {       // 128*24/4
                int r = k / 6, c = (k % 6) * 4;
                *(float4*)&s_cq[r][c]      = gc[k];
                *(float4*)&s_cq[r][24 + c] = gq[k];
            }
            const float2* gb = (const float2*)(g_Bv + (size_t)jb * APAD);
#pragma unroll
            for (int k = tid; k < JCH * 6; k += 128) {       // 128*12/2
                int r = k / 6, c = (k % 6) * 2;
                *(float2*)&s_bj[r][c] = gb[k];
            }
        }
        __syncthreads();

        // --- per-lane: 4 pairs (i, jb + lane + 32x) ---
        u64 h2[4][5];
        float d2s[4], qds[4];
#pragma unroll
        for (int x = 0; x < 4; x++) {
            d2s[x] = 0.f; qds[x] = 0.f;
#pragma unroll
            for (int t = 0; t < 5; t++) {
                u64 ai = *(const u64*)&s_ai[w][2 * t];
                h2[x][t] = f2add(ai, *(const u64*)&s_bj[32 * x + lane][2 * t]);
            }
        }

#pragma unroll
        for (int kk = 0; kk < 6; ++kk) {
            float4 ci4 = *(const float4*)&s_ciq[w][4 * kk];
            float4 qi4 = *(const float4*)&s_ciq[w][24 + 4 * kk];
            float4 cj[4], qj[4];
#pragma unroll
            for (int x = 0; x < 4; x++) {
                cj[x] = *(const float4*)&s_cq[32 * x + lane][4 * kk];
                qj[x] = *(const float4*)&s_cq[32 * x + lane][24 + 4 * kk];
            }
            const float* cip = &ci4.x; const float* qip = &qi4.x;
#pragma unroll
            for (int e = 0; e < 4; e++) {
                const int d = 4 * kk + e;
                u64 av[4];
#pragma unroll
                for (int x = 0; x < 4; x++) {
                    const float* cjp = &cj[x].x;
                    const float* qjp = &qj[x].x;
                    float df = cip[e] - cjp[e];
                    d2s[x] = fmaf(df, df, d2s[x]);              // scalar chain (no pk)
                    qds[x] = fmaf(qip[e], qjp[e], qds[x]);      // scalar chain (no pk)
                    float ad = fabsf(df);
                    av[x] = pk(ad, ad);
                }
#pragma unroll
                for (int t = 0; t < 5; t++) {
                    u64 wv = *(const u64*)&s_w1[d][2 * t];
                    h2[0][t] = f2fma(av[0], wv, h2[0][t]);
                    h2[1][t] = f2fma(av[1], wv, h2[1][t]);
                    h2[2][t] = f2fma(av[2], wv, h2[2][t]);
                    h2[3][t] = f2fma(av[3], wv, h2[3][t]);
                }
            }
        }
        // tail features: q_overlap, coord_dist
        u64 qp[4], dp[4];
#pragma unroll
        for (int x = 0; x < 4; x++) {
            float ds = sqrtf(d2s[x]);
            qp[x] = pk(qds[x], qds[x]);
            dp[x] = pk(ds, ds);
        }
#pragma unroll
        for (int t = 0; t < 5; t++) {
            u64 wq = *(const u64*)&s_w1[24][2 * t];
            u64 wd = *(const u64*)&s_w1[25][2 * t];
#pragma unroll
            for (int x = 0; x < 4; x++) {
                h2[x][t] = f2fma(qp[x], wq, h2[x][t]);
                h2[x][t] = f2fma(dp[x], wd, h2[x][t]);
            }
        }
        // relu -> hidden scalars
        float ha[4][RD];
#pragma unroll
        for (int x = 0; x < 4; x++) {
#pragma unroll
            for (int t = 0; t < 5; t++) {
                float lo, hi;
                upk(lo, hi, h2[x][t]);
                ha[x][2 * t]     = fmaxf(lo, 0.f);
                ha[x][2 * t + 1] = fmaxf(hi, 0.f);
            }
        }

        // layer 2: each weight LDS feeds 4 pairs
        u64 r2[4][5];
#pragma unroll
        for (int x = 0; x < 4; x++)
#pragma unroll
            for (int t = 0; t < 5; t++) r2[x][t] = b2p[t];
#pragma unroll
        for (int rh = 0; rh < RD; rh++) {
            u64 hh[4];
#pragma unroll
            for (int x = 0; x < 4; x++) hh[x] = pk(ha[x][rh], ha[x][rh]);
#pragma unroll
            for (int t = 0; t < 5; t++) {
                u64 wv = *(const u64*)&s_w2[rh][2 * t];
                r2[0][t] = f2fma(hh[0], wv, r2[0][t]);
                r2[1][t] = f2fma(hh[1], wv, r2[1][t]);
                r2[2][t] = f2fma(hh[2], wv, r2[2][t]);
                r2[3][t] = f2fma(hh[3], wv, r2[3][t]);
            }
        }
        // relu + masked accumulate
#pragma unroll
        for (int x = 0; x < 4; x++) {
            const bool off = (jb + 32 * x + lane) != i;
            if (off) {
#pragma unroll
                for (int t = 0; t < 5; t++) {
                    float r0, r1;
                    upk(r0, r1, r2[x][t]);
                    r0 = fmaxf(r0, 0.f); r1 = fmaxf(r1, 0.f);
                    sacc[2 * t]     += r0;  macc[2 * t]     = fmaxf(macc[2 * t], r0);
                    sacc[2 * t + 1] += r1;  macc[2 * t + 1] = fmaxf(macc[2 * t + 1], r1);
                }
            }
        }
    }

    // warp reduction across j-lanes (deterministic tree)
#pragma unroll
    for (int c = 0; c < RD; c++) {
#pragma unroll
        for (int o = 16; o > 0; o >>= 1) {
            sacc[c] += __shfl_xor_sync(0xffffffffu, sacc[c], o);
            macc[c] = fmaxf(macc[c], __shfl_xor_sync(0xffffffffu, macc[c], o));
        }
    }
    if (lane == 0) {
        const float inv = 1.0f / (float)(NSEQ - 1);
#pragma unroll
        for (int c = 0; c < RD; c++) {
            out[(size_t)i * RD + c] = sacc[c] * inv;
            out[(size_t)ROWS * RD + (size_t)i * RD + c] = macc[c];
        }
    }
}

// ---------------------------------------------------------------------------
extern "C" void kernel_launch(void* const* d_in, const int* in_sizes, int n_in,
                              void* d_out, int out_size) {
    const float* x     = (const float*)d_in[0];
    const float* q     = (const float*)d_in[1];
    const float* coord = (const float*)d_in[2];
    const float* W1    = (const float*)d_in[3];
    const float* b1    = (const float*)d_in[4];
    const float* W2    = (const float*)d_in[5];
    const float* b2    = (const float*)d_in[6];
    float* out = (float*)d_out;

    precompute_kernel<<<(ROWS + 127) / 128, 128>>>(x, W1, b1);
    pair_kernel<<<ROWS / 4, 128>>>(q, coord, W1, W2, b2, out);
}